// round 1
// baseline (speedup 1.0000x reference)
#include <cuda_runtime.h>

#define NT   256
#define PPB  4
#define DCONST 64
#define HCONST 2048

// Per-batch a_h = sum_i W2[h,i] * v_i  (supports B up to 64)
__device__ float g_a[64 * HCONST];

__global__ __launch_bounds__(NT) void prep_kernel(
    const float* __restrict__ x0, const float* __restrict__ xT,
    const float* __restrict__ W2, float* __restrict__ out,
    int B, int O, int n_steps)
{
    const int D = DCONST, H = HCONST;
    int b = blockIdx.x;
    int tid = threadIdx.x, lane = tid & 31, warp = tid >> 5;
    __shared__ float v_sh[DCONST];
    __shared__ float inv_sh;

    if (tid < D) v_sh[tid] = xT[b * D + tid] - x0[b * D + tid];
    __syncthreads();
    if (warp == 0) {
        float s = v_sh[lane] * v_sh[lane] + v_sh[lane + 32] * v_sh[lane + 32];
        #pragma unroll
        for (int o = 16; o; o >>= 1) s += __shfl_xor_sync(0xffffffffu, s, o);
        if (lane == 0) inv_sh = 1.0f / sqrtf(s);
    }
    __syncthreads();
    float inv = inv_sh;
    float vl0 = v_sh[lane] * inv;
    float vl1 = v_sh[lane + 32] * inv;

    // a_h = W2[h,:] . v   (rows of W2 are contiguous, warp-per-row)
    for (int h = warp; h < H; h += NT / 32) {
        float partial = W2[h * O + lane] * vl0 + W2[h * O + 32 + lane] * vl1;
        #pragma unroll
        for (int o = 16; o; o >>= 1) partial += __shfl_xor_sync(0xffffffffu, partial, o);
        if (lane == 0) g_a[b * H + h] = partial;
    }

    // boundary rows of the output path
    if (tid < D) {
        out[(0 * B + b) * D + tid] = x0[b * D + tid];
        out[((n_steps - 1) * B + b) * D + tid] = xT[b * D + tid];
    }
}

__global__ __launch_bounds__(NT) void geo_main(
    const float* __restrict__ x0, const float* __restrict__ xT,
    const float* __restrict__ W1, const float* __restrict__ b1,
    float* __restrict__ out, int B, int n_steps, int nInterior)
{
    const int D = DCONST, H = HCONST, H4 = HCONST / 4;
    extern __shared__ float sm[];
    float* as_sh  = sm;                   // PPB*H : a*s, later a*s'*q
    float* asp_sh = sm + PPB * H;         // PPB*H : a*s'
    float* x_sh   = sm + 2 * PPB * H;     // PPB*D : straight-line points
    float* w_sh   = x_sh + PPB * D;       // PPB*D
    float* c_sh   = w_sh + PPB * D;       // PPB*D : raw corr
    float* sc_sh  = c_sh + PPB * D;       // PPB   : 0.1*min(||corr||,0.1)

    int tid = threadIdx.x, lane = tid & 31, warp = tid >> 5;
    int p0 = blockIdx.x * PPB;
    float invn1 = 1.0f / (float)(n_steps - 1);

    int bb[PPB];
    #pragma unroll
    for (int p = 0; p < PPB; ++p) {
        int gp = p0 + p; if (gp >= nInterior) gp = nInterior - 1;
        bb[p] = gp % B;
    }

    // load straight-line interior points
    for (int idx = tid; idx < PPB * D; idx += NT) {
        int p = idx >> 6, m = idx & (D - 1);
        int gp = p0 + p; if (gp >= nInterior) gp = nInterior - 1;
        int s = gp / B + 1;
        int b = gp % B;
        float t = (float)s * invn1;
        float a0 = x0[b * D + m];
        x_sh[idx] = a0 + t * (xT[b * D + m] - a0);
    }
    __syncthreads();

    // ---- pass 1: h_j = x.W1[:,j] + b1_j ; store a*s and a*s' ----
    {
        float hacc[PPB][HCONST / NT];
        #pragma unroll
        for (int k = 0; k < H / NT; ++k) {
            float bj = b1[tid + NT * k];
            #pragma unroll
            for (int p = 0; p < PPB; ++p) hacc[p][k] = bj;
        }
        for (int d = 0; d < D; ++d) {
            float xc[PPB];
            #pragma unroll
            for (int p = 0; p < PPB; ++p) xc[p] = x_sh[p * D + d];
            const float* w1row = W1 + d * H + tid;
            #pragma unroll
            for (int k = 0; k < H / NT; ++k) {
                float w1v = w1row[NT * k];
                #pragma unroll
                for (int p = 0; p < PPB; ++p) hacc[p][k] += xc[p] * w1v;
            }
        }
        #pragma unroll
        for (int k = 0; k < H / NT; ++k) {
            int j = tid + NT * k;
            #pragma unroll
            for (int p = 0; p < PPB; ++p) {
                float a = g_a[bb[p] * H + j];
                float t = tanhf(hacc[p][k]);
                float sfac = 1.0f - t * t;
                as_sh[p * H + j]  = a * sfac;
                asp_sh[p * H + j] = a * (-2.0f * t * sfac);
            }
        }
    }
    __syncthreads();

    // ---- pass 2: w_d = sum_j W1[d,j] * (a*s)_j ----
    {
        float acc[8][PPB];
        #pragma unroll
        for (int dd = 0; dd < 8; ++dd)
            #pragma unroll
            for (int p = 0; p < PPB; ++p) acc[dd][p] = 0.f;
        const float4* W14 = (const float4*)W1;
        const float4* as4 = (const float4*)as_sh;
        #pragma unroll 4
        for (int i = lane; i < H4; i += 32) {
            float4 av[PPB];
            #pragma unroll
            for (int p = 0; p < PPB; ++p) av[p] = as4[p * H4 + i];
            #pragma unroll
            for (int dd = 0; dd < 8; ++dd) {
                float4 wv = W14[(warp * 8 + dd) * H4 + i];
                #pragma unroll
                for (int p = 0; p < PPB; ++p)
                    acc[dd][p] += wv.x * av[p].x + wv.y * av[p].y
                                + wv.z * av[p].z + wv.w * av[p].w;
            }
        }
        #pragma unroll
        for (int dd = 0; dd < 8; ++dd)
            #pragma unroll
            for (int p = 0; p < PPB; ++p) {
                float r = acc[dd][p];
                #pragma unroll
                for (int o = 16; o; o >>= 1) r += __shfl_xor_sync(0xffffffffu, r, o);
                if (lane == 0) w_sh[p * D + warp * 8 + dd] = r;
            }
    }
    __syncthreads();

    // ---- pass 3: q_j = sum_d W1[d,j]*w_d ;  m_j = (a*s')_j * q_j -> as_sh ----
    {
        float qacc[PPB][HCONST / NT];
        #pragma unroll
        for (int k = 0; k < H / NT; ++k)
            #pragma unroll
            for (int p = 0; p < PPB; ++p) qacc[p][k] = 0.f;
        for (int d = 0; d < D; ++d) {
            float wc[PPB];
            #pragma unroll
            for (int p = 0; p < PPB; ++p) wc[p] = w_sh[p * D + d];
            const float* w1row = W1 + d * H + tid;
            #pragma unroll
            for (int k = 0; k < H / NT; ++k) {
                float w1v = w1row[NT * k];
                #pragma unroll
                for (int p = 0; p < PPB; ++p) qacc[p][k] += wc[p] * w1v;
            }
        }
        #pragma unroll
        for (int k = 0; k < H / NT; ++k) {
            int j = tid + NT * k;
            #pragma unroll
            for (int p = 0; p < PPB; ++p)
                as_sh[p * H + j] = asp_sh[p * H + j] * qacc[p][k];
        }
    }
    __syncthreads();

    // ---- pass 4: corr_m = -sum_j W1[m,j] * m_j ----
    {
        float acc[8][PPB];
        #pragma unroll
        for (int dd = 0; dd < 8; ++dd)
            #pragma unroll
            for (int p = 0; p < PPB; ++p) acc[dd][p] = 0.f;
        const float4* W14 = (const float4*)W1;
        const float4* m4 = (const float4*)as_sh;
        #pragma unroll 4
        for (int i = lane; i < H4; i += 32) {
            float4 av[PPB];
            #pragma unroll
            for (int p = 0; p < PPB; ++p) av[p] = m4[p * H4 + i];
            #pragma unroll
            for (int dd = 0; dd < 8; ++dd) {
                float4 wv = W14[(warp * 8 + dd) * H4 + i];
                #pragma unroll
                for (int p = 0; p < PPB; ++p)
                    acc[dd][p] += wv.x * av[p].x + wv.y * av[p].y
                                + wv.z * av[p].z + wv.w * av[p].w;
            }
        }
        #pragma unroll
        for (int dd = 0; dd < 8; ++dd)
            #pragma unroll
            for (int p = 0; p < PPB; ++p) {
                float r = acc[dd][p];
                #pragma unroll
                for (int o = 16; o; o >>= 1) r += __shfl_xor_sync(0xffffffffu, r, o);
                if (lane == 0) c_sh[p * D + warp * 8 + dd] = -r;
            }
    }
    __syncthreads();

    // ---- epilogue: scale = 0.1*min(||corr||,0.1) ; out = straight + corr*t(1-t)*scale ----
    if (warp < PPB) {
        int p = warp;
        float c0 = c_sh[p * D + lane], c1 = c_sh[p * D + 32 + lane];
        float s = c0 * c0 + c1 * c1;
        #pragma unroll
        for (int o = 16; o; o >>= 1) s += __shfl_xor_sync(0xffffffffu, s, o);
        if (lane == 0) sc_sh[p] = fminf(sqrtf(s), 0.1f) * 0.1f;
    }
    __syncthreads();
    for (int idx = tid; idx < PPB * D; idx += NT) {
        int p = idx >> 6, m = idx & (D - 1);
        int gp = p0 + p;
        if (gp < nInterior) {
            int s = gp / B + 1;
            float t = (float)s * invn1;
            float tfac = t * (1.0f - t);
            out[(gp + B) * D + m] = x_sh[idx] + c_sh[idx] * tfac * sc_sh[p];
        }
    }
}

extern "C" void kernel_launch(void* const* d_in, const int* in_sizes, int n_in,
                              void* d_out, int out_size)
{
    const float* x0 = (const float*)d_in[0];
    const float* xT = (const float*)d_in[1];
    const float* W1 = (const float*)d_in[2];
    const float* b1 = (const float*)d_in[3];
    const float* W2 = (const float*)d_in[4];
    float* out = (float*)d_out;

    int H = in_sizes[3];            // 2048
    int Dd = in_sizes[2] / H;       // 64
    int B = in_sizes[0] / Dd;       // 32
    int O = in_sizes[5];            // 64
    int n_steps = out_size / (B * Dd);   // 10
    int nInterior = (n_steps - 2) * B;   // 256

    prep_kernel<<<B, NT>>>(x0, xT, W2, out, B, O, n_steps);

    if (nInterior > 0) {
        int nb = (nInterior + PPB - 1) / PPB;
        size_t smem = (size_t)(2 * PPB * HCONST + 3 * PPB * DCONST + PPB) * sizeof(float);
        cudaFuncSetAttribute(geo_main, cudaFuncAttributeMaxDynamicSharedMemorySize, (int)smem);
        geo_main<<<nb, NT, smem>>>(x0, xT, W1, b1, out, B, n_steps, nInterior);
    }
}

// round 2
// speedup vs baseline: 2.4426x; 2.4426x over previous
#include <cuda_runtime.h>

#define NT    256
#define PPB   2
#define DCONST 64
#define HCONST 2048
#define CCH   256              // chunk columns
#define NCH   (HCONST / CCH)   // 8 chunks

__device__ float g_a[64 * HCONST];   // per-batch a_h = W2[h,:].v

// ------------------------------------------------------------------
// prep: v = normalize(xT-x0); a = W2.v ; boundary rows of out
// grid = B * 8 blocks; block bz: batch b = bz>>3, H-slice = (bz&7)*256
// ------------------------------------------------------------------
__global__ __launch_bounds__(NT) void prep_kernel(
    const float* __restrict__ x0, const float* __restrict__ xT,
    const float* __restrict__ W2, float* __restrict__ out,
    int B, int O, int n_steps)
{
    const int D = DCONST, H = HCONST;
    int b = blockIdx.x >> 3;
    int slice = blockIdx.x & 7;
    int tid = threadIdx.x, lane = tid & 31, warp = tid >> 5;
    __shared__ float v_sh[DCONST];
    __shared__ float inv_sh;

    if (tid < D) v_sh[tid] = xT[b * D + tid] - x0[b * D + tid];
    __syncthreads();
    if (warp == 0) {
        float s = v_sh[lane] * v_sh[lane] + v_sh[lane + 32] * v_sh[lane + 32];
        #pragma unroll
        for (int o = 16; o; o >>= 1) s += __shfl_xor_sync(0xffffffffu, s, o);
        if (lane == 0) inv_sh = 1.0f / sqrtf(s);
    }
    __syncthreads();
    float inv = inv_sh;
    float vl0 = v_sh[lane] * inv;
    float vl1 = v_sh[lane + 32] * inv;

    int h0 = slice * (H / 8);
    for (int h = h0 + warp; h < h0 + H / 8; h += NT / 32) {
        float partial = W2[h * O + lane] * vl0 + W2[h * O + 32 + lane] * vl1;
        #pragma unroll
        for (int o = 16; o; o >>= 1) partial += __shfl_xor_sync(0xffffffffu, partial, o);
        if (lane == 0) g_a[b * H + h] = partial;
    }

    if (slice == 0 && tid < D) {
        out[(0 * B + b) * D + tid] = x0[b * D + tid];
        out[((n_steps - 1) * B + b) * D + tid] = xT[b * D + tid];
    }
}

// ------------------------------------------------------------------
// chunk stage: cp.async one 64x256 f32 tile of W1 into smem
// ------------------------------------------------------------------
__device__ __forceinline__ void load_chunk(float* buf, const float* __restrict__ W1,
                                           int chunk, int tid)
{
    #pragma unroll
    for (int s = 0; s < 16; ++s) {
        int g = s * NT + tid;             // 4096 16B-segments
        int d = g >> 6;                   // row 0..63
        int c16 = g & 63;                 // 16B segment within row
        const float* src = W1 + d * HCONST + chunk * CCH + c16 * 4;
        unsigned dst = (unsigned)__cvta_generic_to_shared(buf + d * CCH + c16 * 4);
        asm volatile("cp.async.cg.shared.global [%0], [%1], 16;" :: "r"(dst), "l"(src));
    }
    asm volatile("cp.async.commit_group;");
}

// ------------------------------------------------------------------
// main: PPB=2 points per block, H chunked through smem, passes fused
// ------------------------------------------------------------------
__global__ __launch_bounds__(NT) void geo_main(
    const float* __restrict__ x0, const float* __restrict__ xT,
    const float* __restrict__ W1, const float* __restrict__ b1,
    float* __restrict__ out, int B, int n_steps, int nInterior)
{
    const int D = DCONST, H = HCONST;
    extern __shared__ float sm[];
    float* w1b0  = sm;                       // 64*256
    float* w1b1  = w1b0 + 64 * CCH;          // 64*256
    float* asp_s = w1b1 + 64 * CCH;          // PPB*H
    float* as_ch = asp_s + PPB * H;          // PPB*CCH  (also m chunk)
    float* xp    = as_ch + PPB * CCH;        // D*PPB  (xp[m*2+p])
    float* wp    = xp + D * PPB;             // D*PPB  (wp[d*2+p])
    float* csh   = wp + D * PPB;             // PPB*D
    float* sc    = csh + PPB * D;            // PPB

    int tid = threadIdx.x, lane = tid & 31, warp = tid >> 5;
    int p0 = blockIdx.x * PPB;
    float invn1 = 1.0f / (float)(n_steps - 1);

    int bb[PPB];
    #pragma unroll
    for (int p = 0; p < PPB; ++p) {
        int gp = p0 + p; if (gp >= nInterior) gp = nInterior - 1;
        bb[p] = gp % B;
    }

    // straight-line points -> xp[m*2+p]
    if (tid < PPB * D) {
        int p = tid >> 6, m = tid & (D - 1);
        int gp = p0 + p; if (gp >= nInterior) gp = nInterior - 1;
        int s = gp / B + 1;
        int b = gp % B;
        float t = (float)s * invn1;
        float a0 = x0[b * D + m];
        xp[m * 2 + p] = a0 + t * (xT[b * D + m] - a0);
    }

    load_chunk(w1b0, W1, 0, tid);
    load_chunk(w1b1, W1, 1, tid);

    float wacc[PPB][8];
    #pragma unroll
    for (int p = 0; p < PPB; ++p)
        #pragma unroll
        for (int r = 0; r < 8; ++r) wacc[p][r] = 0.f;

    // ================= sweep A: h -> as/asp ; w = W1.as =================
    for (int c = 0; c < NCH; ++c) {
        asm volatile("cp.async.wait_group 1;");
        __syncthreads();
        float* W1c = (c & 1) ? w1b1 : w1b0;

        // ---- pass 1 (column): thread <-> j-local = tid
        int j = c * CCH + tid;
        float bj = b1[j];
        float a0 = g_a[bb[0] * H + j];
        float a1 = g_a[bb[1] * H + j];
        float h0 = bj, h1 = bj;
        const float2* xp2 = (const float2*)xp;
        #pragma unroll 8
        for (int d = 0; d < D; ++d) {
            float wv = W1c[d * CCH + tid];
            float2 xc = xp2[d];
            h0 += xc.x * wv;
            h1 += xc.y * wv;
        }
        {
            float t0 = tanhf(h0), t1 = tanhf(h1);
            float s0 = 1.f - t0 * t0, s1 = 1.f - t1 * t1;
            as_ch[tid]        = a0 * s0;
            as_ch[CCH + tid]  = a1 * s1;
            asp_s[j]          = a0 * (-2.f * t0 * s0);
            asp_s[H + j]      = a1 * (-2.f * t1 * s1);
        }
        __syncthreads();

        // ---- pass 2 (row, float4): warp handles rows warp*8..+7
        {
            const float4* W1c4 = (const float4*)W1c;   // [64][64]
            const float4* as4  = (const float4*)as_ch; // [2][64]
            #pragma unroll
            for (int k = 0; k < 2; ++k) {
                float4 v0 = as4[k * 32 + lane];
                float4 v1 = as4[64 + k * 32 + lane];
                #pragma unroll
                for (int r = 0; r < 8; ++r) {
                    float4 wv = W1c4[(warp * 8 + r) * 64 + k * 32 + lane];
                    wacc[0][r] += wv.x * v0.x + wv.y * v0.y + wv.z * v0.z + wv.w * v0.w;
                    wacc[1][r] += wv.x * v1.x + wv.y * v1.y + wv.z * v1.z + wv.w * v1.w;
                }
            }
        }
        __syncthreads();
        if (c + 2 < 2 * NCH) load_chunk((c & 1) ? w1b1 : w1b0, W1, (c + 2) & (NCH - 1), tid);
    }

    // reduce w -> wp[d*2+p]
    #pragma unroll
    for (int r = 0; r < 8; ++r)
        #pragma unroll
        for (int p = 0; p < PPB; ++p) {
            float v = wacc[p][r];
            #pragma unroll
            for (int o = 16; o; o >>= 1) v += __shfl_xor_sync(0xffffffffu, v, o);
            if (lane == 0) wp[(warp * 8 + r) * 2 + p] = v;
        }
    __syncthreads();

    float cacc[PPB][8];
    #pragma unroll
    for (int p = 0; p < PPB; ++p)
        #pragma unroll
        for (int r = 0; r < 8; ++r) cacc[p][r] = 0.f;

    // ================= sweep B: q = w.W1 ; m = asp*q ; corr = -W1.m =====
    for (int c = 0; c < NCH; ++c) {
        int stage = NCH + c;
        asm volatile("cp.async.wait_group 1;");
        __syncthreads();
        float* W1c = (stage & 1) ? w1b1 : w1b0;

        // ---- pass 3 (column)
        int j = c * CCH + tid;
        float q0 = 0.f, q1 = 0.f;
        const float2* wp2 = (const float2*)wp;
        #pragma unroll 8
        for (int d = 0; d < D; ++d) {
            float wv = W1c[d * CCH + tid];
            float2 wc = wp2[d];
            q0 += wc.x * wv;
            q1 += wc.y * wv;
        }
        as_ch[tid]       = asp_s[j] * q0;
        as_ch[CCH + tid] = asp_s[H + j] * q1;
        __syncthreads();

        // ---- pass 4 (row, float4)
        {
            const float4* W1c4 = (const float4*)W1c;
            const float4* m4   = (const float4*)as_ch;
            #pragma unroll
            for (int k = 0; k < 2; ++k) {
                float4 v0 = m4[k * 32 + lane];
                float4 v1 = m4[64 + k * 32 + lane];
                #pragma unroll
                for (int r = 0; r < 8; ++r) {
                    float4 wv = W1c4[(warp * 8 + r) * 64 + k * 32 + lane];
                    cacc[0][r] += wv.x * v0.x + wv.y * v0.y + wv.z * v0.z + wv.w * v0.w;
                    cacc[1][r] += wv.x * v1.x + wv.y * v1.y + wv.z * v1.z + wv.w * v1.w;
                }
            }
        }
        __syncthreads();
        if (stage + 2 < 2 * NCH) load_chunk((stage & 1) ? w1b1 : w1b0, W1, (stage + 2) & (NCH - 1), tid);
    }

    // reduce corr -> csh[p*D+m]  (negated)
    #pragma unroll
    for (int r = 0; r < 8; ++r)
        #pragma unroll
        for (int p = 0; p < PPB; ++p) {
            float v = cacc[p][r];
            #pragma unroll
            for (int o = 16; o; o >>= 1) v += __shfl_xor_sync(0xffffffffu, v, o);
            if (lane == 0) csh[p * D + warp * 8 + r] = -v;
        }
    __syncthreads();

    // scale = 0.1*min(||corr||,0.1)
    if (warp < PPB) {
        int p = warp;
        float c0 = csh[p * D + lane], c1 = csh[p * D + 32 + lane];
        float s = c0 * c0 + c1 * c1;
        #pragma unroll
        for (int o = 16; o; o >>= 1) s += __shfl_xor_sync(0xffffffffu, s, o);
        if (lane == 0) sc[p] = fminf(sqrtf(s), 0.1f) * 0.1f;
    }
    __syncthreads();

    if (tid < PPB * D) {
        int p = tid >> 6, m = tid & (D - 1);
        int gp = p0 + p;
        if (gp < nInterior) {
            int s = gp / B + 1;
            float t = (float)s * invn1;
            float tfac = t * (1.0f - t);
            out[(gp + B) * D + m] = xp[m * 2 + p] + csh[p * D + m] * tfac * sc[p];
        }
    }
}

extern "C" void kernel_launch(void* const* d_in, const int* in_sizes, int n_in,
                              void* d_out, int out_size)
{
    const float* x0 = (const float*)d_in[0];
    const float* xT = (const float*)d_in[1];
    const float* W1 = (const float*)d_in[2];
    const float* b1 = (const float*)d_in[3];
    const float* W2 = (const float*)d_in[4];
    float* out = (float*)d_out;

    int H = in_sizes[3];              // 2048
    int Dd = in_sizes[2] / H;         // 64
    int B = in_sizes[0] / Dd;         // 32
    int O = in_sizes[5];              // 64
    int n_steps = out_size / (B * Dd);// 10
    int nInterior = (n_steps - 2) * B;// 256

    prep_kernel<<<B * 8, NT>>>(x0, xT, W2, out, B, O, n_steps);

    if (nInterior > 0) {
        int nb = (nInterior + PPB - 1) / PPB;   // 128
        size_t smem = (size_t)(2 * 64 * CCH + PPB * HCONST + PPB * CCH
                               + 3 * DCONST * PPB + PPB + 8) * sizeof(float);
        static int attr_set = 0;
        if (!attr_set) {
            cudaFuncSetAttribute(geo_main, cudaFuncAttributeMaxDynamicSharedMemorySize, (int)smem);
            attr_set = 1;
        }
        geo_main<<<nb, NT, smem>>>(x0, xT, W1, b1, out, B, n_steps, nInterior);
    }
}

// round 3
// speedup vs baseline: 2.4515x; 1.0036x over previous
#include <cuda_runtime.h>

#define NT    256
#define PG    4                 // points per group
#define DCONST 64
#define HCONST 2048
#define CCH   256               // chunk columns
#define NCH   (HCONST / CCH)    // 8
#define MAXPTS 1024

__device__ float g_a[64 * HCONST];                 // per-batch a_h = W2[h,:].v
__device__ float g_asp[MAXPTS * HCONST];           // a * s' per point
__device__ float g_wpart[NCH * MAXPTS * DCONST];   // partial w
__device__ float g_cpart[NCH * MAXPTS * DCONST];   // partial corr (unnegated)

// ------------------------------------------------------------------
// prep: v = normalize(xT-x0); a = W2.v ; boundary rows of out
// ------------------------------------------------------------------
__global__ __launch_bounds__(NT) void prep_kernel(
    const float* __restrict__ x0, const float* __restrict__ xT,
    const float* __restrict__ W2, float* __restrict__ out,
    int B, int O, int n_steps)
{
    const int D = DCONST, H = HCONST;
    int b = blockIdx.x >> 3;
    int slice = blockIdx.x & 7;
    int tid = threadIdx.x, lane = tid & 31, warp = tid >> 5;
    __shared__ float v_sh[DCONST];
    __shared__ float inv_sh;

    if (tid < D) v_sh[tid] = xT[b * D + tid] - x0[b * D + tid];
    __syncthreads();
    if (warp == 0) {
        float s = v_sh[lane] * v_sh[lane] + v_sh[lane + 32] * v_sh[lane + 32];
        #pragma unroll
        for (int o = 16; o; o >>= 1) s += __shfl_xor_sync(0xffffffffu, s, o);
        if (lane == 0) inv_sh = 1.0f / sqrtf(s);
    }
    __syncthreads();
    float inv = inv_sh;
    float vl0 = v_sh[lane] * inv;
    float vl1 = v_sh[lane + 32] * inv;

    int h0 = slice * (H / 8);
    for (int h = h0 + warp; h < h0 + H / 8; h += NT / 32) {
        float partial = W2[h * O + lane] * vl0 + W2[h * O + 32 + lane] * vl1;
        #pragma unroll
        for (int o = 16; o; o >>= 1) partial += __shfl_xor_sync(0xffffffffu, partial, o);
        if (lane == 0) g_a[b * H + h] = partial;
    }

    if (slice == 0 && tid < D) {
        out[(0 * B + b) * D + tid] = x0[b * D + tid];
        out[((n_steps - 1) * B + b) * D + tid] = xT[b * D + tid];
    }
}

__device__ __forceinline__ void load_chunk_async(float* buf, const float* __restrict__ W1,
                                                 int j0, int tid)
{
    #pragma unroll
    for (int s = 0; s < 16; ++s) {
        int g = s * NT + tid;            // 4096 16B segments
        int d = g >> 6;
        int k = g & 63;
        const float* src = W1 + d * HCONST + j0 + k * 4;
        unsigned dst = (unsigned)__cvta_generic_to_shared(buf + d * CCH + k * 4);
        asm volatile("cp.async.cg.shared.global [%0], [%1], 16;" :: "r"(dst), "l"(src));
    }
    asm volatile("cp.async.commit_group;");
}

// ------------------------------------------------------------------
// Kernel A: block (g,c) — h -> as/asp ; partial w = W1_chunk . as
// ------------------------------------------------------------------
__global__ __launch_bounds__(NT) void kA(
    const float* __restrict__ x0, const float* __restrict__ xT,
    const float* __restrict__ W1, const float* __restrict__ b1,
    int B, int n_steps, int nInterior)
{
    const int D = DCONST, H = HCONST;
    extern __shared__ float sm[];
    float* W1s  = sm;                    // 64*256
    float* xp4  = sm + D * CCH;          // [d][p] : 256
    float* as_t = xp4 + D * PG;          // [j][p] : 1024

    int tid = threadIdx.x, lane = tid & 31, warp = tid >> 5;
    int g = blockIdx.x, c = blockIdx.y;
    int j0 = c * CCH;
    float invn1 = 1.0f / (float)(n_steps - 1);

    load_chunk_async(W1s, W1, j0, tid);

    int bb[PG], gpc[PG];
    #pragma unroll
    for (int p = 0; p < PG; ++p) {
        int gp = g * PG + p; if (gp >= nInterior) gp = nInterior - 1;
        gpc[p] = gp; bb[p] = gp % B;
    }

    // straight-line points -> xp4[m*PG+p]
    {
        int p = tid >> 6, m = tid & (D - 1);
        int gp = gpc[0] - 0; // recompute properly
        gp = g * PG + p; if (gp >= nInterior) gp = nInterior - 1;
        int s = gp / B + 1;
        int b = gp % B;
        float t = (float)s * invn1;
        float a0 = x0[b * D + m];
        xp4[m * PG + p] = a0 + t * (xT[b * D + m] - a0);
    }

    asm volatile("cp.async.wait_group 0;");
    __syncthreads();

    // column pass: h_j for 4 points
    int j = j0 + tid;
    float bj = b1[j];
    float h0 = bj, h1 = bj, h2 = bj, h3 = bj;
    const float4* xpv = (const float4*)xp4;
    #pragma unroll 8
    for (int d = 0; d < D; ++d) {
        float wv = W1s[d * CCH + tid];
        float4 xv = xpv[d];
        h0 += xv.x * wv; h1 += xv.y * wv; h2 += xv.z * wv; h3 += xv.w * wv;
    }
    {
        float hv[PG] = {h0, h1, h2, h3};
        float asv[PG];
        #pragma unroll
        for (int p = 0; p < PG; ++p) {
            float a = g_a[bb[p] * H + j];
            float t = tanhf(hv[p]);
            float sfac = 1.0f - t * t;
            asv[p] = a * sfac;
            g_asp[gpc[p] * H + j] = a * (-2.0f * t * sfac);
        }
        ((float4*)as_t)[tid] = make_float4(asv[0], asv[1], asv[2], asv[3]);
    }
    __syncthreads();

    // row pass: warp handles rows warp*8..+7
    float acc[8][PG];
    #pragma unroll
    for (int r = 0; r < 8; ++r)
        #pragma unroll
        for (int p = 0; p < PG; ++p) acc[r][p] = 0.f;
    const float4* as4 = (const float4*)as_t;
    #pragma unroll
    for (int jj = 0; jj < 8; ++jj) {
        int j2 = jj * 32 + lane;
        float4 av = as4[j2];
        #pragma unroll
        for (int r = 0; r < 8; ++r) {
            float wv = W1s[(warp * 8 + r) * CCH + j2];
            acc[r][0] += wv * av.x; acc[r][1] += wv * av.y;
            acc[r][2] += wv * av.z; acc[r][3] += wv * av.w;
        }
    }
    #pragma unroll
    for (int r = 0; r < 8; ++r)
        #pragma unroll
        for (int p = 0; p < PG; ++p) {
            float v = acc[r][p];
            #pragma unroll
            for (int o = 16; o; o >>= 1) v += __shfl_xor_sync(0xffffffffu, v, o);
            if (lane == 0)
                g_wpart[(c * MAXPTS + gpc[p]) * D + warp * 8 + r] = v;
        }
}

// ------------------------------------------------------------------
// Kernel B: reduce w ; q = w.W1_chunk ; m = asp*q ; partial corr
// ------------------------------------------------------------------
__global__ __launch_bounds__(NT) void kB(
    const float* __restrict__ W1,
    int B, int nInterior)
{
    const int D = DCONST, H = HCONST;
    extern __shared__ float sm[];
    float* W1s  = sm;                    // 64*256
    float* wp_t = sm + D * CCH;          // [d][p] : 256
    float* m_t  = wp_t + D * PG;         // [j][p] : 1024

    int tid = threadIdx.x, lane = tid & 31, warp = tid >> 5;
    int g = blockIdx.x, c = blockIdx.y;
    int j0 = c * CCH;

    load_chunk_async(W1s, W1, j0, tid);

    int gpc[PG];
    #pragma unroll
    for (int p = 0; p < PG; ++p) {
        int gp = g * PG + p; if (gp >= nInterior) gp = nInterior - 1;
        gpc[p] = gp;
    }

    // reduce w partials: thread (d = tid>>2, p = tid&3)
    {
        int d = tid >> 2, p = tid & 3;
        int gp = gpc[p];
        float s = 0.f;
        #pragma unroll
        for (int cc = 0; cc < NCH; ++cc)
            s += g_wpart[(cc * MAXPTS + gp) * D + d];
        wp_t[tid] = s;                   // layout [d][p]
    }

    asm volatile("cp.async.wait_group 0;");
    __syncthreads();

    // column pass: q_j for 4 points
    int j = j0 + tid;
    float q0 = 0.f, q1 = 0.f, q2 = 0.f, q3 = 0.f;
    const float4* wpv = (const float4*)wp_t;
    #pragma unroll 8
    for (int d = 0; d < D; ++d) {
        float wv = W1s[d * CCH + tid];
        float4 wc = wpv[d];
        q0 += wc.x * wv; q1 += wc.y * wv; q2 += wc.z * wv; q3 += wc.w * wv;
    }
    {
        float a0 = g_asp[gpc[0] * H + j];
        float a1 = g_asp[gpc[1] * H + j];
        float a2 = g_asp[gpc[2] * H + j];
        float a3 = g_asp[gpc[3] * H + j];
        ((float4*)m_t)[tid] = make_float4(a0 * q0, a1 * q1, a2 * q2, a3 * q3);
    }
    __syncthreads();

    // row pass
    float acc[8][PG];
    #pragma unroll
    for (int r = 0; r < 8; ++r)
        #pragma unroll
        for (int p = 0; p < PG; ++p) acc[r][p] = 0.f;
    const float4* m4 = (const float4*)m_t;
    #pragma unroll
    for (int jj = 0; jj < 8; ++jj) {
        int j2 = jj * 32 + lane;
        float4 av = m4[j2];
        #pragma unroll
        for (int r = 0; r < 8; ++r) {
            float wv = W1s[(warp * 8 + r) * CCH + j2];
            acc[r][0] += wv * av.x; acc[r][1] += wv * av.y;
            acc[r][2] += wv * av.z; acc[r][3] += wv * av.w;
        }
    }
    #pragma unroll
    for (int r = 0; r < 8; ++r)
        #pragma unroll
        for (int p = 0; p < PG; ++p) {
            float v = acc[r][p];
            #pragma unroll
            for (int o = 16; o; o >>= 1) v += __shfl_xor_sync(0xffffffffu, v, o);
            if (lane == 0)
                g_cpart[(c * MAXPTS + gpc[p]) * D + warp * 8 + r] = v;
        }
}

// ------------------------------------------------------------------
// Kernel C: reduce corr, scale, epilogue
// ------------------------------------------------------------------
__global__ __launch_bounds__(NT) void kC(
    const float* __restrict__ x0, const float* __restrict__ xT,
    float* __restrict__ out, int B, int n_steps, int nInterior)
{
    const int D = DCONST;
    __shared__ float csh[PG * DCONST];   // [p][d]
    __shared__ float sc[PG];

    int tid = threadIdx.x, lane = tid & 31, warp = tid >> 5;
    int g = blockIdx.x;
    float invn1 = 1.0f / (float)(n_steps - 1);

    {
        int d = tid >> 2, p = tid & 3;
        int gp = g * PG + p; if (gp >= nInterior) gp = nInterior - 1;
        float s = 0.f;
        #pragma unroll
        for (int cc = 0; cc < NCH; ++cc)
            s += g_cpart[(cc * MAXPTS + gp) * D + d];
        csh[p * D + d] = -s;
    }
    __syncthreads();

    if (warp < PG) {
        int p = warp;
        float c0 = csh[p * D + lane], c1 = csh[p * D + 32 + lane];
        float s = c0 * c0 + c1 * c1;
        #pragma unroll
        for (int o = 16; o; o >>= 1) s += __shfl_xor_sync(0xffffffffu, s, o);
        if (lane == 0) sc[p] = fminf(sqrtf(s), 0.1f) * 0.1f;
    }
    __syncthreads();

    {
        int p = tid >> 6, m = tid & (D - 1);
        int gp = g * PG + p;
        if (gp < nInterior) {
            int s = gp / B + 1;
            int b = gp % B;
            float t = (float)s * invn1;
            float a0 = x0[b * D + m];
            float xp = a0 + t * (xT[b * D + m] - a0);
            float tfac = t * (1.0f - t);
            out[(gp + B) * D + m] = xp + csh[p * D + m] * tfac * sc[p];
        }
    }
}

extern "C" void kernel_launch(void* const* d_in, const int* in_sizes, int n_in,
                              void* d_out, int out_size)
{
    const float* x0 = (const float*)d_in[0];
    const float* xT = (const float*)d_in[1];
    const float* W1 = (const float*)d_in[2];
    const float* b1 = (const float*)d_in[3];
    const float* W2 = (const float*)d_in[4];
    float* out = (float*)d_out;

    int H = in_sizes[3];               // 2048
    int Dd = in_sizes[2] / H;          // 64
    int B = in_sizes[0] / Dd;          // 32
    int O = in_sizes[5];               // 64
    int n_steps = out_size / (B * Dd); // 10
    int nInterior = (n_steps - 2) * B; // 256

    prep_kernel<<<B * 8, NT>>>(x0, xT, W2, out, B, O, n_steps);

    if (nInterior > 0) {
        int NG = (nInterior + PG - 1) / PG;      // 64
        size_t smemA = (size_t)(DCONST * CCH + DCONST * PG + CCH * PG) * sizeof(float);
        static int attr_set = 0;
        if (!attr_set) {
            cudaFuncSetAttribute(kA, cudaFuncAttributeMaxDynamicSharedMemorySize, (int)smemA);
            cudaFuncSetAttribute(kB, cudaFuncAttributeMaxDynamicSharedMemorySize, (int)smemA);
            attr_set = 1;
        }
        dim3 grid(NG, NCH);
        kA<<<grid, NT, smemA>>>(x0, xT, W1, b1, B, n_steps, nInterior);
        kB<<<grid, NT, smemA>>>(W1, B, nInterior);
        kC<<<NG, NT>>>(x0, xT, out, B, n_steps, nInterior);
    }
}